// round 8
// baseline (speedup 1.0000x reference)
#include <cuda_runtime.h>
#include <cuda_fp16.h>
#include <cstdint>

#define NB   8
#define CC   256
#define CQK  32
#define LL   4096
#define BI   64
#define BJ   32
#define NJT  (LL / BJ)          // 128 j-tiles
#define INVLN2 1.4426950408889634f

// ---------------- scratch (device globals) ----------------------------------
__device__ float  g_Wt [CC * 320];                  // fused weights, channel-major
__device__ __half g_qh [NB * LL * CQK];             // (N, L, 32) token-major fp16-hi
__device__ __half g_ql [NB * LL * CQK];
__device__ __half g_kh [NB * LL * CQK];             // (N, L, 32) fp16-hi (scaled 1/ln2)
__device__ __half g_kl [NB * LL * CQK];
__device__ __half g_v  [(size_t)NB * 192 * LL];     // V cols 0..191  (fp16, tensor path)
__device__ float  g_v32[(size_t)NB * 64  * LL];     // V cols 192..255 (f32, core path)

// ---------------- helpers ----------------------------------------------------
__device__ __forceinline__ uint32_t smem_u32(const void* p) {
    uint32_t a;
    asm("{ .reg .u64 t; cvta.to.shared.u64 t, %1; cvt.u32.u64 %0, t; }" : "=r"(a) : "l"(p));
    return a;
}
__device__ __forceinline__ void cp_async16(uint32_t dst, const void* src) {
    asm volatile("cp.async.cg.shared.global [%0], [%1], 16;"
                 :: "r"(dst), "l"((unsigned long long)__cvta_generic_to_global(src)) : "memory");
}
#define CP_COMMIT() asm volatile("cp.async.commit_group;" ::: "memory")
#define CP_WAIT0()  asm volatile("cp.async.wait_group 0;" ::: "memory")

__device__ __forceinline__ uint32_t h2u(__half2 h) { return *reinterpret_cast<uint32_t*>(&h); }
__device__ __forceinline__ float ex2f(float x) {
    float r;
    asm("ex2.approx.f32 %0, %1;" : "=f"(r) : "f"(x));
    return r;
}
__device__ __forceinline__ void ldsm_x4(uint32_t& r0, uint32_t& r1, uint32_t& r2, uint32_t& r3,
                                        uint32_t addr) {
    asm volatile("ldmatrix.sync.aligned.m8n8.x4.shared.b16 {%0,%1,%2,%3}, [%4];"
                 : "=r"(r0), "=r"(r1), "=r"(r2), "=r"(r3) : "r"(addr));
}
__device__ __forceinline__ void mma_f16(float c[4], const uint32_t a[4],
                                        uint32_t b0, uint32_t b1) {
    asm("mma.sync.aligned.m16n8k16.row.col.f32.f16.f16.f32 "
        "{%0,%1,%2,%3}, {%4,%5,%6,%7}, {%8,%9}, {%0,%1,%2,%3};"
        : "+f"(c[0]), "+f"(c[1]), "+f"(c[2]), "+f"(c[3])
        : "r"(a[0]), "r"(a[1]), "r"(a[2]), "r"(a[3]), "r"(b0), "r"(b1));
}
// packed f32x2 ops (FMA pipe)
typedef unsigned long long u64;
__device__ __forceinline__ u64 pack2(float a, float b) {
    u64 r; asm("mov.b64 %0, {%1, %2};" : "=l"(r) : "f"(a), "f"(b)); return r;
}
__device__ __forceinline__ void unpack2(u64 v, float& lo, float& hi) {
    asm("mov.b64 {%0, %1}, %2;" : "=f"(lo), "=f"(hi) : "l"(v));
}
__device__ __forceinline__ void ffma2(u64& d, u64 a, u64 b) {
    asm("fma.rn.f32x2 %0, %1, %2, %0;" : "+l"(d) : "l"(a), "l"(b));
}
__device__ __forceinline__ void fmul2(u64& d, u64 a) {
    asm("mul.rn.f32x2 %0, %1, %0;" : "+l"(d) : "l"(a));
}
__device__ __forceinline__ u64 h2tof2(uint32_t h) {
    float2 f = __half22float2(*reinterpret_cast<__half2*>(&h));
    return pack2(f.x, f.y);
}

// ---------------- kernel 1: weight transpose ---------------------------------
__global__ void wtrans_kernel(const float* __restrict__ Wq,
                              const float* __restrict__ Wk,
                              const float* __restrict__ Wv) {
    int idx = blockIdx.x * 256 + threadIdx.x;
    if (idx >= 320 * 256) return;
    int o = idx >> 8, c = idx & 255;
    float v;
    if (o < 32)       v = Wq[o * 256 + c];
    else if (o < 64)  v = Wk[(o - 32) * 256 + c];
    else              v = Wv[(o - 64) * 256 + c];
    g_Wt[c * 320 + o] = v;
}

// ---------------- kernel 2: fused QKV projection -----------------------------
__global__ __launch_bounds__(256, 1)
void proj_kernel(const float* __restrict__ x,
                 const float* __restrict__ bq,
                 const float* __restrict__ bk,
                 const float* __restrict__ bv) {
    extern __shared__ float xs[];   // [256][128]
    const int n  = blockIdx.y;
    const int l0 = blockIdx.x * 128;
    const int tid = threadIdx.x;

    const float* xb = x + ((size_t)n << 20) + l0;
    #pragma unroll 4
    for (int idx = tid; idx < 256 * 128; idx += 256) {
        int c = idx >> 7, l = idx & 127;
        xs[idx] = xb[(c << 12) + l];
    }
    __syncthreads();

    const int warp = tid >> 5, lane = tid & 31;
    const int lb = lane * 4;

    for (int og = 0; og < 10; og++) {
        const int obase = og * 32 + warp * 4;
        float bias[4];
        #pragma unroll
        for (int r = 0; r < 4; r++) {
            int o = obase + r;
            bias[r] = (o < 32) ? bq[o] : (o < 64) ? bk[o - 32] : bv[o - 64];
        }
        float4 acc0 = make_float4(bias[0], bias[0], bias[0], bias[0]);
        float4 acc1 = make_float4(bias[1], bias[1], bias[1], bias[1]);
        float4 acc2 = make_float4(bias[2], bias[2], bias[2], bias[2]);
        float4 acc3 = make_float4(bias[3], bias[3], bias[3], bias[3]);

        #pragma unroll 4
        for (int c = 0; c < 256; c++) {
            float4 w  = __ldg((const float4*)&g_Wt[c * 320 + obase]);
            float4 xv = *(const float4*)&xs[c * 128 + lb];
            acc0.x += w.x * xv.x; acc0.y += w.x * xv.y; acc0.z += w.x * xv.z; acc0.w += w.x * xv.w;
            acc1.x += w.y * xv.x; acc1.y += w.y * xv.y; acc1.z += w.y * xv.z; acc1.w += w.y * xv.w;
            acc2.x += w.z * xv.x; acc2.y += w.z * xv.y; acc2.z += w.z * xv.z; acc2.w += w.z * xv.w;
            acc3.x += w.w * xv.x; acc3.y += w.w * xv.y; acc3.z += w.w * xv.z; acc3.w += w.w * xv.w;
        }
        float4 acc[4] = {acc0, acc1, acc2, acc3};

        if (obase < 64) {
            const bool isQ = (obase < 32);
            __half* dsth = isQ ? g_qh : g_kh;
            __half* dstl = isQ ? g_ql : g_kl;
            const float sc = isQ ? 1.0f : INVLN2;   // K carries 1/ln2 -> exp2 domain
            const int ob = obase & 31;
            #pragma unroll
            for (int s = 0; s < 4; s++) {
                float v0 = (&acc[0].x)[s] * sc, v1 = (&acc[1].x)[s] * sc;
                float v2 = (&acc[2].x)[s] * sc, v3 = (&acc[3].x)[s] * sc;
                __half h0 = __float2half_rn(v0), h1 = __float2half_rn(v1);
                __half h2 = __float2half_rn(v2), h3 = __float2half_rn(v3);
                __half e0 = __float2half_rn(v0 - __half2float(h0));
                __half e1 = __float2half_rn(v1 - __half2float(h1));
                __half e2 = __float2half_rn(v2 - __half2float(h2));
                __half e3 = __float2half_rn(v3 - __half2float(h3));
                size_t base = ((size_t)((n << 12) + l0 + lb + s)) * 32 + ob;
                ((__half2*)(dsth + base))[0] = __halves2half2(h0, h1);
                ((__half2*)(dsth + base))[1] = __halves2half2(h2, h3);
                ((__half2*)(dstl + base))[0] = __halves2half2(e0, e1);
                ((__half2*)(dstl + base))[1] = __halves2half2(e2, e3);
            }
        } else if (obase < 256) {
            // V cols 0..191 -> fp16 (tensor path)
            const int vo = obase - 64;
            #pragma unroll
            for (int r = 0; r < 4; r++) {
                float4 a = acc[r];
                size_t base = (((size_t)n * 192 + vo + r) << 12) + l0 + lb;
                ((__half2*)(g_v + base))[0] = __floats2half2_rn(a.x, a.y);
                ((__half2*)(g_v + base))[1] = __floats2half2_rn(a.z, a.w);
            }
        } else {
            // V cols 192..255 -> f32 (core path, exact)
            const int vo = obase - 256;
            #pragma unroll
            for (int r = 0; r < 4; r++) {
                *(float4*)&g_v32[(((size_t)n * 64 + vo + r) << 12) + l0 + lb] = acc[r];
            }
        }
    }
}

// ---------------- kernel 3: hybrid tensor+core flash attention ---------------
// fp16 rows padded to 40 halfs (80 B); f32 V rows padded to 36 floats (144 B);
// P relay rows 136 B (17 u64) so strided u64 reads are conflict-free.
#define OFF_QH 0            // [64][40] fp16
#define OFF_QL 5120
#define OFF_K  10240        // 2 slots x 5120: [KH 32][40] then [KL 32][40]
#define OFF_V  20480        // 2 slots x 15360: [192][40] fp16 (cols 0..191)
#define OFF_W  51200        // 2 slots x  9216: [64][36] f32  (cols 192..255)
#define OFF_P  69632        // 4 warps x 2176: [16 rows][16 jpairs] f32x2, 136 B/row
#define ATTN_SMEM 78336

__device__ __forceinline__ void loadK(uint32_t smb, int n, int j0, int slot, int tid) {
    const uint32_t kbase = smb + OFF_K + slot * 5120;
    #pragma unroll
    for (int it = 0; it < 2; it++) {
        int idx = it * 128 + tid;        // 0..255
        int hl = idx >> 7;
        int r  = (idx >> 2) & 31;
        int s  = idx & 3;
        const __half* src = (hl ? g_kl : g_kh) + ((size_t)((n << 12) + j0 + r)) * 32 + s * 8;
        cp_async16(kbase + hl * 2560 + r * 80 + s * 16, src);
    }
}
__device__ __forceinline__ void loadV(uint32_t smb, int n, int j0, int slot, int tid) {
    const uint32_t vbase = smb + OFF_V + slot * 15360;
    #pragma unroll
    for (int it = 0; it < 6; it++) {
        int idx = it * 128 + tid;        // 0..767
        int cr = idx >> 2;               // 0..191
        int s  = idx & 3;
        const __half* src = g_v + (((size_t)n * 192 + cr) << 12) + j0 + s * 8;
        cp_async16(vbase + cr * 80 + s * 16, src);
    }
    const uint32_t wbase = smb + OFF_W + slot * 9216;
    #pragma unroll
    for (int it = 0; it < 4; it++) {
        int idx = it * 128 + tid;        // 0..511
        int cr = idx >> 3;               // 0..63
        int s  = idx & 7;
        const float* src = g_v32 + (((size_t)n * 64 + cr) << 12) + j0 + s * 4;
        cp_async16(wbase + cr * 144 + s * 16, src);
    }
}

__global__ __launch_bounds__(128, 2)
void attn_kernel(const float* __restrict__ x,
                 const float* __restrict__ gamma,
                 float* __restrict__ out) {
    extern __shared__ char sm[];
    const uint32_t smb = smem_u32(sm);
    const int tid  = threadIdx.x;
    const int wid  = tid >> 5, lane = tid & 31;
    const int g    = lane >> 2, m = lane & 3;
    const int iw   = wid * 16;
    const int n    = blockIdx.y;
    const int i0   = blockIdx.x * BI;

    const uint32_t aoff = (uint32_t)((lane & 7) * 80 + (lane >> 3) * 16);

    // ---- prologue: Q + tile 0 ----
    #pragma unroll
    for (int it = 0; it < 4; it++) {
        int idx  = it * 128 + tid;          // 0..511
        int half = idx >> 8;
        int r    = (idx >> 2) & 63;
        int s    = idx & 3;
        const __half* src = (half ? g_ql : g_qh) + ((size_t)((n << 12) + i0 + r)) * 32 + s * 8;
        cp_async16(smb + (half ? OFF_QL : OFF_QH) + r * 80 + s * 16, src);
    }
    loadK(smb, n, 0, 0, tid);
    loadV(smb, n, 0, 0, tid);
    CP_COMMIT();

    uint32_t qh[2][4], ql[2][4];
    float O[24][4];                       // tensor half: cols 0..191
    #pragma unroll
    for (int nt = 0; nt < 24; nt++)
        #pragma unroll
        for (int e = 0; e < 4; e++) O[nt][e] = 0.f;
    u64 A0[16], A1[16];                   // core half: rows iw+g / iw+g+8, ch 192+4cc+m
    #pragma unroll
    for (int cc = 0; cc < 16; cc++) { A0[cc] = 0ull; A1[cc] = 0ull; }
    float mr0 = -1e30f, mr1 = -1e30f, lr0 = 0.f, lr1 = 0.f;

    for (int jt = 0; jt < NJT; jt++) {
        const int cur = jt & 1;
        CP_WAIT0();
        __syncthreads();
        if (jt + 1 < NJT) {
            loadK(smb, n, (jt + 1) * BJ, 1 - cur, tid);
            loadV(smb, n, (jt + 1) * BJ, 1 - cur, tid);
        }
        CP_COMMIT();

        if (jt == 0) {
            const uint32_t* QHw = (const uint32_t*)(sm + OFF_QH);
            const uint32_t* QLw = (const uint32_t*)(sm + OFF_QL);
            #pragma unroll
            for (int kc = 0; kc < 2; kc++) {
                qh[kc][0] = QHw[(iw + g)     * 20 + 8 * kc + m];
                qh[kc][1] = QHw[(iw + g + 8) * 20 + 8 * kc + m];
                qh[kc][2] = QHw[(iw + g)     * 20 + 8 * kc + 4 + m];
                qh[kc][3] = QHw[(iw + g + 8) * 20 + 8 * kc + 4 + m];
                ql[kc][0] = QLw[(iw + g)     * 20 + 8 * kc + m];
                ql[kc][1] = QLw[(iw + g + 8) * 20 + 8 * kc + m];
                ql[kc][2] = QLw[(iw + g)     * 20 + 8 * kc + 4 + m];
                ql[kc][3] = QLw[(iw + g + 8) * 20 + 8 * kc + 4 + m];
            }
        }

        // ---- S = Q K^T (3-term fp16 split) ----
        const uint32_t kb = smb + OFF_K + cur * 5120;
        float C[4][4];
        #pragma unroll
        for (int nt = 0; nt < 4; nt++) {
            C[nt][0] = C[nt][1] = C[nt][2] = C[nt][3] = 0.f;
            uint32_t h0, h1, h2, h3, e0, e1, e2, e3;
            ldsm_x4(h0, h1, h2, h3, kb + nt * 640 + aoff);
            ldsm_x4(e0, e1, e2, e3, kb + 2560 + nt * 640 + aoff);
            mma_f16(C[nt], qh[0], h0, h1);  mma_f16(C[nt], ql[0], h0, h1);  mma_f16(C[nt], qh[0], e0, e1);
            mma_f16(C[nt], qh[1], h2, h3);  mma_f16(C[nt], ql[1], h2, h3);  mma_f16(C[nt], qh[1], e2, e3);
        }

        // ---- softmax, exp2 domain ----
        float t0 = -1e30f, t1 = -1e30f;
        #pragma unroll
        for (int nt = 0; nt < 4; nt++) {
            t0 = fmaxf(t0, fmaxf(C[nt][0], C[nt][1]));
            t1 = fmaxf(t1, fmaxf(C[nt][2], C[nt][3]));
        }
        t0 = fmaxf(t0, __shfl_xor_sync(0xffffffffu, t0, 1));
        t0 = fmaxf(t0, __shfl_xor_sync(0xffffffffu, t0, 2));
        t1 = fmaxf(t1, __shfl_xor_sync(0xffffffffu, t1, 1));
        t1 = fmaxf(t1, __shfl_xor_sync(0xffffffffu, t1, 2));
        float mn0 = fmaxf(mr0, t0), mn1 = fmaxf(mr1, t1);
        float al0 = ex2f(mr0 - mn0), al1 = ex2f(mr1 - mn1);
        mr0 = mn0; mr1 = mn1;

        uint32_t P[4][2];
        float rs0 = 0.f, rs1 = 0.f;
        #pragma unroll
        for (int nt = 0; nt < 4; nt++) {
            float p0 = ex2f(C[nt][0] - mn0), p1 = ex2f(C[nt][1] - mn0);
            float p2 = ex2f(C[nt][2] - mn1), p3 = ex2f(C[nt][3] - mn1);
            __half2 h01 = __floats2half2_rn(p0, p1);
            __half2 h23 = __floats2half2_rn(p2, p3);
            P[nt][0] = h2u(h01); P[nt][1] = h2u(h23);
            float2 f01 = __half22float2(h01), f23 = __half22float2(h23);
            rs0 += f01.x + f01.y; rs1 += f23.x + f23.y;
        }
        rs0 += __shfl_xor_sync(0xffffffffu, rs0, 1);
        rs0 += __shfl_xor_sync(0xffffffffu, rs0, 2);
        rs1 += __shfl_xor_sync(0xffffffffu, rs1, 1);
        rs1 += __shfl_xor_sync(0xffffffffu, rs1, 2);
        lr0 = lr0 * al0 + rs0;
        lr1 = lr1 * al1 + rs1;

        // ---- publish P (fp16-rounded, as f32 pairs) to per-warp relay ----
        {
            char* pb = sm + OFF_P + wid * 2176;
            #pragma unroll
            for (int nt = 0; nt < 4; nt++) {
                int s = 4 * nt + m;          // jpair slot = (8nt+2m)/2
                *(u64*)(pb + g * 136 + s * 8)       = h2tof2(P[nt][0]);   // row g
                *(u64*)(pb + (g + 8) * 136 + s * 8) = h2tof2(P[nt][1]);   // row g+8
            }
        }
        __syncwarp();

        // ---- rescale accumulators ----
        if (__any_sync(0xffffffffu, (al0 != 1.f) || (al1 != 1.f))) {
            #pragma unroll
            for (int nt = 0; nt < 24; nt++) {
                O[nt][0] *= al0; O[nt][1] *= al0;
                O[nt][2] *= al1; O[nt][3] *= al1;
            }
            u64 a0 = pack2(al0, al0), a1 = pack2(al1, al1);
            #pragma unroll
            for (int cc = 0; cc < 16; cc++) { fmul2(A0[cc], a0); fmul2(A1[cc], a1); }
        }

        // ---- tensor PV: cols 0..191 ----
        uint32_t pa0[4] = { P[0][0], P[0][1], P[1][0], P[1][1] };
        uint32_t pa1[4] = { P[2][0], P[2][1], P[3][0], P[3][1] };
        const uint32_t vb = smb + OFF_V + cur * 15360;
        #pragma unroll
        for (int nt = 0; nt < 24; nt++) {
            uint32_t b00, b01, b10, b11;
            ldsm_x4(b00, b01, b10, b11, vb + nt * 640 + aoff);
            mma_f16(O[nt], pa0, b00, b01);
            mma_f16(O[nt], pa1, b10, b11);
        }

        // ---- core PV: cols 192..255 (f32 V, packed FFMA2, exclusive coverage) ----
        {
            const char* wp = sm + OFF_W + cur * 9216;
            const char* pp = sm + OFF_P + wid * 2176;
            #pragma unroll 4
            for (int jp = 0; jp < 16; jp++) {
                u64 p0 = *(const u64*)(pp + g * 136 + jp * 8);
                u64 p1 = *(const u64*)(pp + (g + 8) * 136 + jp * 8);
                #pragma unroll
                for (int cc = 0; cc < 16; cc++) {
                    u64 v = *(const u64*)(wp + (4 * cc + m) * 144 + jp * 8);
                    ffma2(A0[cc], p0, v);
                    ffma2(A1[cc], p1, v);
                }
            }
        }
        __syncwarp();   // relay reads done before next tile overwrites
    }

    // ---- epilogue ----
    const float linv0 = 1.0f / lr0;
    const float linv1 = 1.0f / lr1;
    const float gam = __ldg(gamma);
    // tensor half: cols 0..191
    #pragma unroll
    for (int nt = 0; nt < 24; nt++) {
        #pragma unroll
        for (int e = 0; e < 4; e++) {
            int c   = 8 * nt + 2 * m + (e & 1);
            int row = iw + g + 8 * (e >> 1);
            size_t idx = (((size_t)(n * CC + c)) << 12) + i0 + row;
            float o = O[nt][e] * ((e >> 1) ? linv1 : linv0);
            out[idx] = gam * o + __ldg(&x[idx]);
        }
    }
    // core half: cols 192..255, rows iw+g and iw+g+8
    #pragma unroll
    for (int cc = 0; cc < 16; cc++) {
        int c = 192 + 4 * cc + m;
        float lo, hi;
        unpack2(A0[cc], lo, hi);
        size_t idx0 = (((size_t)(n * CC + c)) << 12) + i0 + iw + g;
        out[idx0] = gam * ((lo + hi) * linv0) + __ldg(&x[idx0]);
        unpack2(A1[cc], lo, hi);
        size_t idx1 = idx0 + 8;
        out[idx1] = gam * ((lo + hi) * linv1) + __ldg(&x[idx1]);
    }
}

// ---------------- launch -----------------------------------------------------
extern "C" void kernel_launch(void* const* d_in, const int* in_sizes, int n_in,
                              void* d_out, int out_size) {
    const float* x     = (const float*)d_in[0];
    const float* Wq    = (const float*)d_in[1];
    const float* bq    = (const float*)d_in[2];
    const float* Wk    = (const float*)d_in[3];
    const float* bk    = (const float*)d_in[4];
    const float* Wv    = (const float*)d_in[5];
    const float* bv    = (const float*)d_in[6];
    const float* gamma = (const float*)d_in[7];
    float* out = (float*)d_out;

    cudaFuncSetAttribute(proj_kernel, cudaFuncAttributeMaxDynamicSharedMemorySize, 131072);
    cudaFuncSetAttribute(attn_kernel, cudaFuncAttributeMaxDynamicSharedMemorySize, ATTN_SMEM);

    wtrans_kernel<<<(320 * 256 + 255) / 256, 256>>>(Wq, Wk, Wv);
    proj_kernel<<<dim3(LL / 128, NB), 256, 131072>>>(x, bq, bk, bv);
    attn_kernel<<<dim3(LL / BI, NB), 128, ATTN_SMEM>>>(x, gamma, out);
}

// round 9
// speedup vs baseline: 2.7843x; 2.7843x over previous
#include <cuda_runtime.h>
#include <cuda_fp16.h>
#include <cstdint>

#define NB   8
#define CC   256
#define CQK  32
#define LL   4096
#define BI   64
#define BJ   32
#define NJT  (LL / BJ)          // 128 j-tiles
#define INVLN2 1.4426950408889634f

// ---------------- scratch (device globals) ----------------------------------
__device__ __half g_Wh [320 * 256];                 // fused weights fp16-hi, (o, c)
__device__ __half g_Wql[64 * 256];                  // fp16-lo residual, q/k rows only
__device__ __half g_qh [NB * LL * CQK];             // (N, L, 32) token-major fp16-hi
__device__ __half g_ql [NB * LL * CQK];
__device__ __half g_kh [NB * LL * CQK];             // (N, L, 32) fp16-hi (scaled 1/ln2)
__device__ __half g_kl [NB * LL * CQK];
__device__ __half g_v  [(size_t)NB * CC * LL];      // (N, C, L) fp16, l contiguous

// ---------------- helpers ----------------------------------------------------
__device__ __forceinline__ uint32_t smem_u32(const void* p) {
    uint32_t a;
    asm("{ .reg .u64 t; cvta.to.shared.u64 t, %1; cvt.u32.u64 %0, t; }" : "=r"(a) : "l"(p));
    return a;
}
__device__ __forceinline__ void cp_async16(uint32_t dst, const void* src) {
    asm volatile("cp.async.cg.shared.global [%0], [%1], 16;"
                 :: "r"(dst), "l"((unsigned long long)__cvta_generic_to_global(src)) : "memory");
}
#define CP_COMMIT() asm volatile("cp.async.commit_group;" ::: "memory")
#define CP_WAIT0()  asm volatile("cp.async.wait_group 0;" ::: "memory")
#define CP_WAIT1()  asm volatile("cp.async.wait_group 1;" ::: "memory")

__device__ __forceinline__ uint32_t h2u(__half2 h) { return *reinterpret_cast<uint32_t*>(&h); }
__device__ __forceinline__ float ex2f(float x) {
    float r;
    asm("ex2.approx.f32 %0, %1;" : "=f"(r) : "f"(x));
    return r;
}
__device__ __forceinline__ void ldsm_x4(uint32_t& r0, uint32_t& r1, uint32_t& r2, uint32_t& r3,
                                        uint32_t addr) {
    asm volatile("ldmatrix.sync.aligned.m8n8.x4.shared.b16 {%0,%1,%2,%3}, [%4];"
                 : "=r"(r0), "=r"(r1), "=r"(r2), "=r"(r3) : "r"(addr));
}
__device__ __forceinline__ void ldsm_x4a(uint32_t r[4], uint32_t addr) {
    ldsm_x4(r[0], r[1], r[2], r[3], addr);
}
__device__ __forceinline__ void mma_f16(float c[4], const uint32_t a[4],
                                        uint32_t b0, uint32_t b1) {
    asm("mma.sync.aligned.m16n8k16.row.col.f32.f16.f16.f32 "
        "{%0,%1,%2,%3}, {%4,%5,%6,%7}, {%8,%9}, {%0,%1,%2,%3};"
        : "+f"(c[0]), "+f"(c[1]), "+f"(c[2]), "+f"(c[3])
        : "r"(a[0]), "r"(a[1]), "r"(a[2]), "r"(a[3]), "r"(b0), "r"(b1));
}

// ---------------- kernel 1: weight prep (fp16 hi + q/k lo residual) ----------
__global__ void wtrans_kernel(const float* __restrict__ Wq,
                              const float* __restrict__ Wk,
                              const float* __restrict__ Wv) {
    int idx = blockIdx.x * 256 + threadIdx.x;
    if (idx >= 320 * 256) return;
    int o = idx >> 8, c = idx & 255;
    float v;
    if (o < 32)       v = Wq[o * 256 + c];
    else if (o < 64)  v = Wk[(o - 32) * 256 + c];
    else              v = Wv[(o - 64) * 256 + c];
    __half h = __float2half_rn(v);
    g_Wh[o * 256 + c] = h;
    if (o < 64) g_Wql[o * 256 + c] = __float2half_rn(v - __half2float(h));
}

// ---------------- kernel 2: tensor-core fused QKV projection ------------------
// grid (L/64, 5, N): blockIdx.y = o-tile (0 = q/k, 1..4 = v channels)
// x smem [64 l][264 halfs] hi+lo; W streamed in 3 slots of [64 o][40 halfs] (32 c).
#define PJ_XH 0
#define PJ_XL 33792
#define PJ_WH 67584        // 3 slots x 5120
#define PJ_WL 82944        // 3 slots x 5120 (q/k CTAs only)
#define PROJ_SMEM 98304

__global__ __launch_bounds__(128, 2)
void proj_kernel(const float* __restrict__ x,
                 const float* __restrict__ bq,
                 const float* __restrict__ bk,
                 const float* __restrict__ bv) {
    extern __shared__ char sm[];
    const uint32_t smb = smem_u32(sm);
    const int tid = threadIdx.x;
    const int wid = tid >> 5, lane = tid & 31;
    const int g = lane >> 2, m = lane & 3;
    const int n = blockIdx.z;
    const int oidx = blockIdx.y;
    const int l0 = blockIdx.x * 64;
    const int obase = oidx * 64;
    const bool qk = (oidx == 0);

    // ---- W slot loader: round r covers c in [r*32, r*32+32) ----
    auto issueW = [&](int r, int slot) {
        #pragma unroll
        for (int k = 0; k < 2; k++) {
            int idx = tid * 2 + k;          // 0..255
            int row = idx >> 2, seg = idx & 3;
            cp_async16(smb + PJ_WH + slot * 5120 + row * 80 + seg * 16,
                       g_Wh + (obase + row) * 256 + r * 32 + seg * 8);
            if (qk)
                cp_async16(smb + PJ_WL + slot * 5120 + row * 80 + seg * 16,
                           g_Wql + row * 256 + r * 32 + seg * 8);
        }
        CP_COMMIT();
    };
    issueW(0, 0);
    issueW(1, 1);

    // ---- convert + transpose x tile: f32 (c,l) -> fp16 hi/lo [l][264] ----
    {
        const float* xb = x + ((size_t)n << 20) + l0;
        const int l = tid & 63, p0 = tid >> 6;
        #pragma unroll 4
        for (int i = 0; i < 64; i++) {
            int p = p0 + 2 * i;             // c-pair index 0..127
            int c = 2 * p;
            float f0 = __ldg(&xb[(size_t)c * 4096 + l]);
            float f1 = __ldg(&xb[(size_t)(c + 1) * 4096 + l]);
            __half h0 = __float2half_rn(f0), h1 = __float2half_rn(f1);
            __half e0 = __float2half_rn(f0 - __half2float(h0));
            __half e1 = __float2half_rn(f1 - __half2float(h1));
            *(uint32_t*)(sm + PJ_XH + l * 528 + p * 4) = h2u(__halves2half2(h0, h1));
            *(uint32_t*)(sm + PJ_XL + l * 528 + p * 4) = h2u(__halves2half2(e0, e1));
        }
    }

    float C[8][4];
    #pragma unroll
    for (int og = 0; og < 8; og++)
        #pragma unroll
        for (int e = 0; e < 4; e++) C[og][e] = 0.f;

    const uint32_t aoffA = (uint32_t)((lane & 15) * 528 + (lane >> 4) * 16);
    const uint32_t aoffB = (uint32_t)((lane & 7) * 80 + (lane >> 3) * 16);
    const uint32_t abase = smb + (uint32_t)(wid * 16) * 528;

    for (int r = 0; r < 8; r++) {
        const int slot = r % 3;
        if (r == 7) { CP_WAIT0(); } else { CP_WAIT1(); }
        __syncthreads();
        if (r + 2 < 8) issueW(r + 2, (r + 2) % 3);

        uint32_t axh0[4], axh1[4], axl0[4], axl1[4];
        ldsm_x4a(axh0, abase + PJ_XH + r * 64 + aoffA);
        ldsm_x4a(axh1, abase + PJ_XH + r * 64 + 32 + aoffA);
        ldsm_x4a(axl0, abase + PJ_XL + r * 64 + aoffA);
        ldsm_x4a(axl1, abase + PJ_XL + r * 64 + 32 + aoffA);

        const uint32_t wb  = smb + PJ_WH + slot * 5120;
        const uint32_t wlb = smb + PJ_WL + slot * 5120;
        #pragma unroll
        for (int og = 0; og < 8; og++) {
            uint32_t b0, b1, b2, b3;
            ldsm_x4(b0, b1, b2, b3, wb + og * 640 + aoffB);
            mma_f16(C[og], axh0, b0, b1);
            mma_f16(C[og], axl0, b0, b1);
            mma_f16(C[og], axh1, b2, b3);
            mma_f16(C[og], axl1, b2, b3);
            if (qk) {
                uint32_t c0, c1, c2, c3;
                ldsm_x4(c0, c1, c2, c3, wlb + og * 640 + aoffB);
                mma_f16(C[og], axh0, c0, c1);
                mma_f16(C[og], axh1, c2, c3);
            }
        }
    }
    __syncthreads();

    if (qk) {
        // ---- q/k epilogue: token-major u32 half2 stores + hi/lo split ----
        #pragma unroll
        for (int og = 0; og < 8; og++) {
            int ol = og * 8 + 2 * m;
            bool isq = (ol < 32);
            float sc = isq ? 1.0f : INVLN2;
            const float* bias = isq ? bq : bk;
            int bo = isq ? ol : ol - 32;
            float b0 = __ldg(&bias[bo]), b1 = __ldg(&bias[bo + 1]);
            uint32_t* dsth = (uint32_t*)(isq ? g_qh : g_kh);
            uint32_t* dstl = (uint32_t*)(isq ? g_ql : g_kl);
            int col = (isq ? og * 4 : (og - 4) * 4) + m;
            #pragma unroll
            for (int rr = 0; rr < 2; rr++) {
                float f0 = (C[og][2 * rr]     + b0) * sc;
                float f1 = (C[og][2 * rr + 1] + b1) * sc;
                __half h0 = __float2half_rn(f0), h1 = __float2half_rn(f1);
                __half e0 = __float2half_rn(f0 - __half2float(h0));
                __half e1 = __float2half_rn(f1 - __half2float(h1));
                size_t lg = (size_t)(n << 12) + l0 + wid * 16 + g + 8 * rr;
                dsth[lg * 16 + col] = h2u(__halves2half2(h0, h1));
                dstl[lg * 16 + col] = h2u(__halves2half2(e0, e1));
            }
        }
    } else {
        // ---- v epilogue: bounce through smem -> coalesced channel-major ----
        __half* bo = (__half*)sm;            // [64 o][72 l]
        const int vb0 = (oidx - 1) * 64;
        #pragma unroll
        for (int og = 0; og < 8; og++) {
            int ol = og * 8 + 2 * m;
            float b0 = __ldg(&bv[vb0 + ol]), b1 = __ldg(&bv[vb0 + ol + 1]);
            int lg = wid * 16 + g;
            bo[ol * 72 + lg]           = __float2half_rn(C[og][0] + b0);
            bo[(ol + 1) * 72 + lg]     = __float2half_rn(C[og][1] + b1);
            bo[ol * 72 + lg + 8]       = __float2half_rn(C[og][2] + b0);
            bo[(ol + 1) * 72 + lg + 8] = __float2half_rn(C[og][3] + b1);
        }
        __syncthreads();
        const int o = tid >> 1, lh = tid & 1;
        const uint4* src = (const uint4*)(sm + o * 144 + lh * 64);
        uint4* dst = (uint4*)(g_v + (((size_t)(n * CC + vb0 + o)) << 12) + l0 + lh * 32);
        #pragma unroll
        for (int i = 0; i < 4; i++) dst[i] = src[i];
    }
}

// ---------------- kernel 3: pipelined fp16 mma flash attention (R6) ----------
#define OFF_QH 0            // [64][40] fp16
#define OFF_QL 5120
#define OFF_K  10240        // 3 slots x 5120: [KH 32][40] then [KL 32][40]
#define OFF_V  25600        // 2 slots x 20480: [256][40] fp16
#define ATTN_SMEM 66560

__device__ __forceinline__ void loadK(uint32_t smb, int n, int j0, int slot, int tid) {
    const uint32_t kbase = smb + OFF_K + slot * 5120;
    #pragma unroll
    for (int it = 0; it < 2; it++) {
        int idx = it * 128 + tid;        // 0..255
        int hl = idx >> 7;
        int r  = (idx >> 2) & 31;
        int s  = idx & 3;
        const __half* src = (hl ? g_kl : g_kh) + ((size_t)((n << 12) + j0 + r)) * 32 + s * 8;
        cp_async16(kbase + hl * 2560 + r * 80 + s * 16, src);
    }
}
__device__ __forceinline__ void loadV(uint32_t smb, int n, int j0, int slot, int tid) {
    const uint32_t vbase = smb + OFF_V + slot * 20480;
    #pragma unroll
    for (int it = 0; it < 8; it++) {
        int idx = it * 128 + tid;        // 0..1023
        int cr = idx >> 2;
        int s  = idx & 3;
        const __half* src = g_v + (((size_t)n * CC + cr) << 12) + j0 + s * 8;
        cp_async16(vbase + cr * 80 + s * 16, src);
    }
}

__global__ __launch_bounds__(128, 2)
void attn_kernel(const float* __restrict__ x,
                 const float* __restrict__ gamma,
                 float* __restrict__ out) {
    extern __shared__ char sm[];
    const uint32_t smb = smem_u32(sm);
    const int tid  = threadIdx.x;
    const int wid  = tid >> 5, lane = tid & 31;
    const int g    = lane >> 2, m = lane & 3;
    const int iw   = wid * 16;
    const int n    = blockIdx.y;
    const int i0   = blockIdx.x * BI;

    const uint32_t aoff = (uint32_t)((lane & 7) * 80 + (lane >> 3) * 16);

    // ---- prologue: Q + K(0) + K(1) + V(0), one commit group ----
    #pragma unroll
    for (int it = 0; it < 4; it++) {
        int idx  = it * 128 + tid;          // 0..511
        int half = idx >> 8;
        int r    = (idx >> 2) & 63;
        int s    = idx & 3;
        const __half* src = (half ? g_ql : g_qh) + ((size_t)((n << 12) + i0 + r)) * 32 + s * 8;
        cp_async16(smb + (half ? OFF_QL : OFF_QH) + r * 80 + s * 16, src);
    }
    loadK(smb, n, 0, 0, tid);
    loadK(smb, n, BJ, 1, tid);
    loadV(smb, n, 0, 0, tid);
    CP_COMMIT();

    uint32_t qh[2][4], ql[2][4];
    float O[32][4];
    #pragma unroll
    for (int nt = 0; nt < 32; nt++)
        #pragma unroll
        for (int e = 0; e < 4; e++) O[nt][e] = 0.f;
    float mr0 = -1e30f, mr1 = -1e30f, lr0 = 0.f, lr1 = 0.f;

    float Cb[2][4][4];
    int ks_next = 1;   // K slot of tile jt+1

    #pragma unroll 2
    for (int jt = 0; jt < NJT; jt++) {
        CP_WAIT0();
        __syncthreads();
        // prefetch K(jt+2), V(jt+1)
        if (jt + 2 < NJT) {
            int ks2 = ks_next + 1; if (ks2 == 3) ks2 = 0;
            loadK(smb, n, (jt + 2) * BJ, ks2, tid);
        }
        if (jt + 1 < NJT) loadV(smb, n, (jt + 1) * BJ, 1 - (jt & 1), tid);
        CP_COMMIT();

        if (jt == 0) {
            const uint32_t* QHw = (const uint32_t*)(sm + OFF_QH);
            const uint32_t* QLw = (const uint32_t*)(sm + OFF_QL);
            #pragma unroll
            for (int kc = 0; kc < 2; kc++) {
                qh[kc][0] = QHw[(iw + g)     * 20 + 8 * kc + m];
                qh[kc][1] = QHw[(iw + g + 8) * 20 + 8 * kc + m];
                qh[kc][2] = QHw[(iw + g)     * 20 + 8 * kc + 4 + m];
                qh[kc][3] = QHw[(iw + g + 8) * 20 + 8 * kc + 4 + m];
                ql[kc][0] = QLw[(iw + g)     * 20 + 8 * kc + m];
                ql[kc][1] = QLw[(iw + g + 8) * 20 + 8 * kc + m];
                ql[kc][2] = QLw[(iw + g)     * 20 + 8 * kc + 4 + m];
                ql[kc][3] = QLw[(iw + g + 8) * 20 + 8 * kc + 4 + m];
            }
            const uint32_t kb = smb + OFF_K;
            #pragma unroll
            for (int nt = 0; nt < 4; nt++) {
                float* C = Cb[0][nt];
                C[0] = C[1] = C[2] = C[3] = 0.f;
                uint32_t h0, h1, h2, h3, e0, e1, e2, e3;
                ldsm_x4(h0, h1, h2, h3, kb + nt * 640 + aoff);
                ldsm_x4(e0, e1, e2, e3, kb + 2560 + nt * 640 + aoff);
                mma_f16(C, qh[0], h0, h1);  mma_f16(C, ql[0], h0, h1);  mma_f16(C, qh[0], e0, e1);
                mma_f16(C, qh[1], h2, h3);  mma_f16(C, ql[1], h2, h3);  mma_f16(C, qh[1], e2, e3);
            }
        }

        // ---- S(jt+1) into the other C buffer (overlaps softmax below) ----
        if (jt + 1 < NJT) {
            const uint32_t kb = smb + OFF_K + ks_next * 5120;
            #pragma unroll
            for (int nt = 0; nt < 4; nt++) {
                float* C = Cb[(jt + 1) & 1][nt];
                C[0] = C[1] = C[2] = C[3] = 0.f;
                uint32_t h0, h1, h2, h3, e0, e1, e2, e3;
                ldsm_x4(h0, h1, h2, h3, kb + nt * 640 + aoff);
                ldsm_x4(e0, e1, e2, e3, kb + 2560 + nt * 640 + aoff);
                mma_f16(C, qh[0], h0, h1);  mma_f16(C, ql[0], h0, h1);  mma_f16(C, qh[0], e0, e1);
                mma_f16(C, qh[1], h2, h3);  mma_f16(C, ql[1], h2, h3);  mma_f16(C, qh[1], e2, e3);
            }
            if (++ks_next == 3) ks_next = 0;
        }

        // ---- softmax(jt) in exp2 domain ----
        float (*C)[4] = Cb[jt & 1];
        float t0 = -1e30f, t1 = -1e30f;
        #pragma unroll
        for (int nt = 0; nt < 4; nt++) {
            t0 = fmaxf(t0, fmaxf(C[nt][0], C[nt][1]));
            t1 = fmaxf(t1, fmaxf(C[nt][2], C[nt][3]));
        }
        t0 = fmaxf(t0, __shfl_xor_sync(0xffffffffu, t0, 1));
        t0 = fmaxf(t0, __shfl_xor_sync(0xffffffffu, t0, 2));
        t1 = fmaxf(t1, __shfl_xor_sync(0xffffffffu, t1, 1));
        t1 = fmaxf(t1, __shfl_xor_sync(0xffffffffu, t1, 2));
        float mn0 = fmaxf(mr0, t0), mn1 = fmaxf(mr1, t1);
        float al0 = ex2f(mr0 - mn0), al1 = ex2f(mr1 - mn1);
        mr0 = mn0; mr1 = mn1;

        uint32_t P[4][2];
        float rs0 = 0.f, rs1 = 0.f;
        #pragma unroll
        for (int nt = 0; nt < 4; nt++) {
            float p0 = ex2f(C[nt][0] - mn0), p1 = ex2f(C[nt][1] - mn0);
            float p2 = ex2f(C[nt][2] - mn1), p3 = ex2f(C[nt][3] - mn1);
            __half2 h01 = __floats2half2_rn(p0, p1);
            __half2 h23 = __floats2half2_rn(p2, p3);
            P[nt][0] = h2u(h01); P[nt][1] = h2u(h23);
            float2 f01 = __half22float2(h01), f23 = __half22float2(h23);
            rs0 += f01.x + f01.y; rs1 += f23.x + f23.y;
        }
        rs0 += __shfl_xor_sync(0xffffffffu, rs0, 1);
        rs0 += __shfl_xor_sync(0xffffffffu, rs0, 2);
        rs1 += __shfl_xor_sync(0xffffffffu, rs1, 1);
        rs1 += __shfl_xor_sync(0xffffffffu, rs1, 2);
        lr0 = lr0 * al0 + rs0;
        lr1 = lr1 * al1 + rs1;

        if (__any_sync(0xffffffffu, (al0 != 1.f) || (al1 != 1.f))) {
            #pragma unroll
            for (int nt = 0; nt < 32; nt++) {
                O[nt][0] *= al0; O[nt][1] *= al0;
                O[nt][2] *= al1; O[nt][3] *= al1;
            }
        }

        // ---- O += P V (ldmatrix.x4 per nt: 4 B-frags in one op) ----
        uint32_t pa0[4] = { P[0][0], P[0][1], P[1][0], P[1][1] };
        uint32_t pa1[4] = { P[2][0], P[2][1], P[3][0], P[3][1] };
        const uint32_t vb = smb + OFF_V + (jt & 1) * 20480;
        #pragma unroll
        for (int nt = 0; nt < 32; nt++) {
            uint32_t b00, b01, b10, b11;
            ldsm_x4(b00, b01, b10, b11, vb + nt * 640 + aoff);
            mma_f16(O[nt], pa0, b00, b01);
            mma_f16(O[nt], pa1, b10, b11);
        }
    }

    // ---- epilogue ----
    const float linv0 = 1.0f / lr0;
    const float linv1 = 1.0f / lr1;
    const float gam = __ldg(gamma);
    #pragma unroll
    for (int nt = 0; nt < 32; nt++) {
        #pragma unroll
        for (int e = 0; e < 4; e++) {
            int c   = 8 * nt + 2 * m + (e & 1);
            int row = iw + g + 8 * (e >> 1);
            size_t idx = (((size_t)(n * CC + c)) << 12) + i0 + row;
            float o = O[nt][e] * ((e >> 1) ? linv1 : linv0);
            out[idx] = gam * o + __ldg(&x[idx]);
        }
    }
}

// ---------------- launch -----------------------------------------------------
extern "C" void kernel_launch(void* const* d_in, const int* in_sizes, int n_in,
                              void* d_out, int out_size) {
    const float* x     = (const float*)d_in[0];
    const float* Wq    = (const float*)d_in[1];
    const float* bq    = (const float*)d_in[2];
    const float* Wk    = (const float*)d_in[3];
    const float* bk    = (const float*)d_in[4];
    const float* Wv    = (const float*)d_in[5];
    const float* bv    = (const float*)d_in[6];
    const float* gamma = (const float*)d_in[7];
    float* out = (float*)d_out;

    cudaFuncSetAttribute(proj_kernel, cudaFuncAttributeMaxDynamicSharedMemorySize, PROJ_SMEM);
    cudaFuncSetAttribute(attn_kernel, cudaFuncAttributeMaxDynamicSharedMemorySize, ATTN_SMEM);

    wtrans_kernel<<<320, 256>>>(Wq, Wk, Wv);
    proj_kernel<<<dim3(LL / 64, 5, NB), 128, PROJ_SMEM>>>(x, bq, bk, bv);
    attn_kernel<<<dim3(LL / BI, NB), 128, ATTN_SMEM>>>(x, gamma, out);
}

// round 11
// speedup vs baseline: 2.8917x; 1.0385x over previous
#include <cuda_runtime.h>
#include <cuda_fp16.h>
#include <cstdint>

#define NB   8
#define CC   256
#define CQK  32
#define LL   4096
#define BI   64
#define BJ   32
#define NJT  (LL / BJ)          // 128 j-tiles
#define INVLN2 1.4426950408889634f

// ---------------- scratch (device globals) ----------------------------------
__device__ __half g_Wh [320 * 256];                 // fused weights fp16-hi, (o, c)
__device__ __half g_Wql[64 * 256];                  // fp16-lo residual, q/k rows only
__device__ __half g_qh [NB * LL * CQK];             // (N, L, 32) token-major fp16-hi
__device__ __half g_ql [NB * LL * CQK];
__device__ __half g_kh [NB * LL * CQK];             // (N, L, 32) fp16-hi (scaled 1/ln2)
__device__ __half g_kl [NB * LL * CQK];
__device__ __half g_v  [(size_t)NB * CC * LL];      // (N, C, L) fp16, l contiguous

// ---------------- helpers ----------------------------------------------------
__device__ __forceinline__ uint32_t smem_u32(const void* p) {
    uint32_t a;
    asm("{ .reg .u64 t; cvta.to.shared.u64 t, %1; cvt.u32.u64 %0, t; }" : "=r"(a) : "l"(p));
    return a;
}
__device__ __forceinline__ void cp_async16(uint32_t dst, const void* src) {
    asm volatile("cp.async.cg.shared.global [%0], [%1], 16;"
                 :: "r"(dst), "l"((unsigned long long)__cvta_generic_to_global(src)) : "memory");
}
#define CP_COMMIT() asm volatile("cp.async.commit_group;" ::: "memory")
#define CP_WAIT0()  asm volatile("cp.async.wait_group 0;" ::: "memory")
#define CP_WAIT1()  asm volatile("cp.async.wait_group 1;" ::: "memory")

// mbarrier (sm_80+/sm_90 baseline PTX; no arch-'a' features)
#define MBARRIER_INIT(mbar, cnt) \
    asm volatile("mbarrier.init.shared.b64 [%0], %1;" :: "r"((uint32_t)(mbar)), "r"((uint32_t)(cnt)) : "memory")
#define MBAR_ARRIVE(mbar) \
    asm volatile("mbarrier.arrive.shared::cta.b64 _, [%0];" :: "r"((uint32_t)(mbar)) : "memory")
// NOTE: .noinc is load-bearing. The default form pre-increments the pending
// count (net zero on the phase) and deadlocks the full[] barriers.
#define CP_MBAR_ARRIVE(mbar) \
    asm volatile("cp.async.mbarrier.arrive.noinc.shared::cta.b64 [%0];" :: "r"((uint32_t)(mbar)) : "memory")
#define MBARRIER_WAIT_PARITY(mbar, parity) do { \
    uint32_t _m = (uint32_t)(mbar); uint32_t _p = (uint32_t)(parity); uint32_t _d; \
    asm volatile("{\n\t.reg .pred p;\n\t" \
        "mbarrier.try_wait.parity.acquire.cta.shared::cta.b64 p, [%1], %2;\n\t" \
        "selp.b32 %0, 1, 0, p;\n\t}" : "=r"(_d) : "r"(_m), "r"(_p) : "memory"); \
    if (!_d) { \
        asm volatile("{\n\t.reg .pred P1;\n\t" \
            "WAIT_LOOP_%=:\n\t" \
            "mbarrier.try_wait.parity.acquire.cta.shared::cta.b64 P1, [%0], %1, 0x989680;\n\t" \
            "@P1 bra.uni WAIT_DONE_%=;\n\t" \
            "bra.uni WAIT_LOOP_%=;\n\t" \
            "WAIT_DONE_%=:\n\t}" :: "r"(_m), "r"(_p) : "memory"); \
    } \
} while (0)

__device__ __forceinline__ uint32_t h2u(__half2 h) { return *reinterpret_cast<uint32_t*>(&h); }
__device__ __forceinline__ float ex2f(float x) {
    float r;
    asm("ex2.approx.f32 %0, %1;" : "=f"(r) : "f"(x));
    return r;
}
__device__ __forceinline__ void ldsm_x4(uint32_t& r0, uint32_t& r1, uint32_t& r2, uint32_t& r3,
                                        uint32_t addr) {
    asm volatile("ldmatrix.sync.aligned.m8n8.x4.shared.b16 {%0,%1,%2,%3}, [%4];"
                 : "=r"(r0), "=r"(r1), "=r"(r2), "=r"(r3) : "r"(addr));
}
__device__ __forceinline__ void ldsm_x4a(uint32_t r[4], uint32_t addr) {
    ldsm_x4(r[0], r[1], r[2], r[3], addr);
}
__device__ __forceinline__ void mma_f16(float c[4], const uint32_t a[4],
                                        uint32_t b0, uint32_t b1) {
    asm("mma.sync.aligned.m16n8k16.row.col.f32.f16.f16.f32 "
        "{%0,%1,%2,%3}, {%4,%5,%6,%7}, {%8,%9}, {%0,%1,%2,%3};"
        : "+f"(c[0]), "+f"(c[1]), "+f"(c[2]), "+f"(c[3])
        : "r"(a[0]), "r"(a[1]), "r"(a[2]), "r"(a[3]), "r"(b0), "r"(b1));
}

// ---------------- kernel 1: weight prep (fp16 hi + q/k lo residual) ----------
__global__ void wtrans_kernel(const float* __restrict__ Wq,
                              const float* __restrict__ Wk,
                              const float* __restrict__ Wv) {
    int idx = blockIdx.x * 256 + threadIdx.x;
    if (idx >= 320 * 256) return;
    int o = idx >> 8, c = idx & 255;
    float v;
    if (o < 32)       v = Wq[o * 256 + c];
    else if (o < 64)  v = Wk[(o - 32) * 256 + c];
    else              v = Wv[(o - 64) * 256 + c];
    __half h = __float2half_rn(v);
    g_Wh[o * 256 + c] = h;
    if (o < 64) g_Wql[o * 256 + c] = __float2half_rn(v - __half2float(h));
}

// ---------------- kernel 2: tensor-core fused QKV projection ------------------
#define PJ_XH 0
#define PJ_XL 33792
#define PJ_WH 67584        // 3 slots x 5120
#define PJ_WL 82944        // 3 slots x 5120 (q/k CTAs only)
#define PROJ_SMEM 98304

__global__ __launch_bounds__(128, 2)
void proj_kernel(const float* __restrict__ x,
                 const float* __restrict__ bq,
                 const float* __restrict__ bk,
                 const float* __restrict__ bv) {
    extern __shared__ char sm[];
    const uint32_t smb = smem_u32(sm);
    const int tid = threadIdx.x;
    const int wid = tid >> 5, lane = tid & 31;
    const int g = lane >> 2, m = lane & 3;
    const int n = blockIdx.z;
    const int oidx = blockIdx.y;
    const int l0 = blockIdx.x * 64;
    const int obase = oidx * 64;
    const bool qk = (oidx == 0);

    auto issueW = [&](int r, int slot) {
        #pragma unroll
        for (int k = 0; k < 2; k++) {
            int idx = tid * 2 + k;          // 0..255
            int row = idx >> 2, seg = idx & 3;
            cp_async16(smb + PJ_WH + slot * 5120 + row * 80 + seg * 16,
                       g_Wh + (obase + row) * 256 + r * 32 + seg * 8);
            if (qk)
                cp_async16(smb + PJ_WL + slot * 5120 + row * 80 + seg * 16,
                           g_Wql + row * 256 + r * 32 + seg * 8);
        }
        CP_COMMIT();
    };
    issueW(0, 0);
    issueW(1, 1);

    {
        const float* xb = x + ((size_t)n << 20) + l0;
        const int l = tid & 63, p0 = tid >> 6;
        #pragma unroll 4
        for (int i = 0; i < 64; i++) {
            int p = p0 + 2 * i;
            int c = 2 * p;
            float f0 = __ldg(&xb[(size_t)c * 4096 + l]);
            float f1 = __ldg(&xb[(size_t)(c + 1) * 4096 + l]);
            __half h0 = __float2half_rn(f0), h1 = __float2half_rn(f1);
            __half e0 = __float2half_rn(f0 - __half2float(h0));
            __half e1 = __float2half_rn(f1 - __half2float(h1));
            *(uint32_t*)(sm + PJ_XH + l * 528 + p * 4) = h2u(__halves2half2(h0, h1));
            *(uint32_t*)(sm + PJ_XL + l * 528 + p * 4) = h2u(__halves2half2(e0, e1));
        }
    }

    float C[8][4];
    #pragma unroll
    for (int og = 0; og < 8; og++)
        #pragma unroll
        for (int e = 0; e < 4; e++) C[og][e] = 0.f;

    const uint32_t aoffA = (uint32_t)((lane & 15) * 528 + (lane >> 4) * 16);
    const uint32_t aoffB = (uint32_t)((lane & 7) * 80 + (lane >> 3) * 16);
    const uint32_t abase = smb + (uint32_t)(wid * 16) * 528;

    for (int r = 0; r < 8; r++) {
        const int slot = r % 3;
        if (r == 7) { CP_WAIT0(); } else { CP_WAIT1(); }
        __syncthreads();
        if (r + 2 < 8) issueW(r + 2, (r + 2) % 3);

        uint32_t axh0[4], axh1[4], axl0[4], axl1[4];
        ldsm_x4a(axh0, abase + PJ_XH + r * 64 + aoffA);
        ldsm_x4a(axh1, abase + PJ_XH + r * 64 + 32 + aoffA);
        ldsm_x4a(axl0, abase + PJ_XL + r * 64 + aoffA);
        ldsm_x4a(axl1, abase + PJ_XL + r * 64 + 32 + aoffA);

        const uint32_t wb  = smb + PJ_WH + slot * 5120;
        const uint32_t wlb = smb + PJ_WL + slot * 5120;
        #pragma unroll
        for (int og = 0; og < 8; og++) {
            uint32_t b0, b1, b2, b3;
            ldsm_x4(b0, b1, b2, b3, wb + og * 640 + aoffB);
            mma_f16(C[og], axh0, b0, b1);
            mma_f16(C[og], axl0, b0, b1);
            mma_f16(C[og], axh1, b2, b3);
            mma_f16(C[og], axl1, b2, b3);
            if (qk) {
                uint32_t c0, c1, c2, c3;
                ldsm_x4(c0, c1, c2, c3, wlb + og * 640 + aoffB);
                mma_f16(C[og], axh0, c0, c1);
                mma_f16(C[og], axh1, c2, c3);
            }
        }
    }
    __syncthreads();

    if (qk) {
        #pragma unroll
        for (int og = 0; og < 8; og++) {
            int ol = og * 8 + 2 * m;
            bool isq = (ol < 32);
            float sc = isq ? 1.0f : INVLN2;
            const float* bias = isq ? bq : bk;
            int bo = isq ? ol : ol - 32;
            float b0 = __ldg(&bias[bo]), b1 = __ldg(&bias[bo + 1]);
            uint32_t* dsth = (uint32_t*)(isq ? g_qh : g_kh);
            uint32_t* dstl = (uint32_t*)(isq ? g_ql : g_kl);
            int col = (isq ? og * 4 : (og - 4) * 4) + m;
            #pragma unroll
            for (int rr = 0; rr < 2; rr++) {
                float f0 = (C[og][2 * rr]     + b0) * sc;
                float f1 = (C[og][2 * rr + 1] + b1) * sc;
                __half h0 = __float2half_rn(f0), h1 = __float2half_rn(f1);
                __half e0 = __float2half_rn(f0 - __half2float(h0));
                __half e1 = __float2half_rn(f1 - __half2float(h1));
                size_t lg = (size_t)(n << 12) + l0 + wid * 16 + g + 8 * rr;
                dsth[lg * 16 + col] = h2u(__halves2half2(h0, h1));
                dstl[lg * 16 + col] = h2u(__halves2half2(e0, e1));
            }
        }
    } else {
        __half* bo = (__half*)sm;            // [64 o][72 l]
        const int vb0 = (oidx - 1) * 64;
        #pragma unroll
        for (int og = 0; og < 8; og++) {
            int ol = og * 8 + 2 * m;
            float b0 = __ldg(&bv[vb0 + ol]), b1 = __ldg(&bv[vb0 + ol + 1]);
            int lg = wid * 16 + g;
            bo[ol * 72 + lg]           = __float2half_rn(C[og][0] + b0);
            bo[(ol + 1) * 72 + lg]     = __float2half_rn(C[og][1] + b1);
            bo[ol * 72 + lg + 8]       = __float2half_rn(C[og][2] + b0);
            bo[(ol + 1) * 72 + lg + 8] = __float2half_rn(C[og][3] + b1);
        }
        __syncthreads();
        const int o = tid >> 1, lh = tid & 1;
        const uint4* src = (const uint4*)(sm + o * 144 + lh * 64);
        uint4* dst = (uint4*)(g_v + (((size_t)(n * CC + vb0 + o)) << 12) + l0 + lh * 32);
        #pragma unroll
        for (int i = 0; i < 4; i++) dst[i] = src[i];
    }
}

// ---------------- kernel 3: mbarrier-skewed fp16 mma flash attention ---------
// No per-tile __syncthreads: 3-deep K/V ring with full/empty mbarriers; warps
// drift up to ~1 tile so softmax hides under other warps' MMA bursts.
#define OFF_QH 0            // [64][40] fp16
#define OFF_QL 5120
#define OFF_K  10240        // 3 slots x 5120: [KH 32][40] then [KL 32][40]
#define OFF_V  25600        // 3 slots x 20480: [256][40] fp16
#define OFF_MB 87040        // full[0..2] at +0, empty[0..2] at +24
#define ATTN_SMEM 87296

__device__ __forceinline__ void loadK(uint32_t smb, int n, int j0, int slot, int tid) {
    const uint32_t kbase = smb + OFF_K + slot * 5120;
    #pragma unroll
    for (int it = 0; it < 2; it++) {
        int idx = it * 128 + tid;        // 0..255
        int hl = idx >> 7;
        int r  = (idx >> 2) & 31;
        int s  = idx & 3;
        const __half* src = (hl ? g_kl : g_kh) + ((size_t)((n << 12) + j0 + r)) * 32 + s * 8;
        cp_async16(kbase + hl * 2560 + r * 80 + s * 16, src);
    }
}
__device__ __forceinline__ void loadV(uint32_t smb, int n, int j0, int slot, int tid) {
    const uint32_t vbase = smb + OFF_V + slot * 20480;
    #pragma unroll
    for (int it = 0; it < 8; it++) {
        int idx = it * 128 + tid;        // 0..1023
        int cr = idx >> 2;
        int s  = idx & 3;
        const __half* src = g_v + (((size_t)n * CC + cr) << 12) + j0 + s * 8;
        cp_async16(vbase + cr * 80 + s * 16, src);
    }
}

__global__ __launch_bounds__(128, 2)
void attn_kernel(const float* __restrict__ x,
                 const float* __restrict__ gamma,
                 float* __restrict__ out) {
    extern __shared__ char sm[];
    const uint32_t smb = smem_u32(sm);
    const int tid  = threadIdx.x;
    const int wid  = tid >> 5, lane = tid & 31;
    const int g    = lane >> 2, m = lane & 3;
    const int iw   = wid * 16;
    const int n    = blockIdx.y;
    const int i0   = blockIdx.x * BI;

    const uint32_t aoff = (uint32_t)((lane & 7) * 80 + (lane >> 3) * 16);
    const uint32_t mb_full  = smb + OFF_MB;
    const uint32_t mb_empty = smb + OFF_MB + 24;

    if (tid == 0) {
        #pragma unroll
        for (int s = 0; s < 3; s++) {
            MBARRIER_INIT(mb_full + 8 * s, 128);
            MBARRIER_INIT(mb_empty + 8 * s, 4);
        }
    }

    // ---- Q tile via plain ld/st (ready after the single syncthreads) ----
    #pragma unroll
    for (int it = 0; it < 4; it++) {
        int idx  = it * 128 + tid;          // 0..511
        int half = idx >> 8;
        int r    = (idx >> 2) & 63;
        int s    = idx & 3;
        const __half* src = (half ? g_ql : g_qh) + ((size_t)((n << 12) + i0 + r)) * 32 + s * 8;
        uint4 v = *(const uint4*)src;
        *(uint4*)(sm + (half ? OFF_QL : OFF_QH) + r * 80 + s * 16) = v;
    }
    __syncthreads();   // mbarrier init + Q visible to all warps

    // ---- prologue: fill slots 0..2 (tiles 0..2), all 128 threads ----
    #pragma unroll
    for (int t = 0; t < 3; t++) {
        loadK(smb, n, t * BJ, t, tid);
        loadV(smb, n, t * BJ, t, tid);
        CP_MBAR_ARRIVE(mb_full + 8 * t);
    }

    // ---- Q fragments ----
    uint32_t qh[2][4], ql[2][4];
    {
        const uint32_t* QHw = (const uint32_t*)(sm + OFF_QH);
        const uint32_t* QLw = (const uint32_t*)(sm + OFF_QL);
        #pragma unroll
        for (int kc = 0; kc < 2; kc++) {
            qh[kc][0] = QHw[(iw + g)     * 20 + 8 * kc + m];
            qh[kc][1] = QHw[(iw + g + 8) * 20 + 8 * kc + m];
            qh[kc][2] = QHw[(iw + g)     * 20 + 8 * kc + 4 + m];
            qh[kc][3] = QHw[(iw + g + 8) * 20 + 8 * kc + 4 + m];
            ql[kc][0] = QLw[(iw + g)     * 20 + 8 * kc + m];
            ql[kc][1] = QLw[(iw + g + 8) * 20 + 8 * kc + m];
            ql[kc][2] = QLw[(iw + g)     * 20 + 8 * kc + 4 + m];
            ql[kc][3] = QLw[(iw + g + 8) * 20 + 8 * kc + 4 + m];
        }
    }

    float O[32][4];
    #pragma unroll
    for (int nt = 0; nt < 32; nt++)
        #pragma unroll
        for (int e = 0; e < 4; e++) O[nt][e] = 0.f;
    float mr0 = -1e30f, mr1 = -1e30f, lr0 = 0.f, lr1 = 0.f;

    for (int jt = 0; jt < NJT; jt++) {
        const int s = jt % 3;

        // ---- per-warp prefetch of tile jt+2 (slot reuse gated by empty[]) ----
        if (jt >= 1 && jt + 2 < NJT) {
            const int t2 = jt + 2;
            const int s2 = t2 % 3;
            MBARRIER_WAIT_PARITY(mb_empty + 8 * s2, (uint32_t)((t2 / 3 - 1) & 1));
            loadK(smb, n, t2 * BJ, s2, tid);
            loadV(smb, n, t2 * BJ, s2, tid);
            CP_MBAR_ARRIVE(mb_full + 8 * s2);
        }

        // ---- wait data ----
        MBARRIER_WAIT_PARITY(mb_full + 8 * s, (uint32_t)((jt / 3) & 1));

        // ---- S = Q K^T (3-term fp16 split) ----
        const uint32_t kb = smb + OFF_K + s * 5120;
        float C[4][4];
        #pragma unroll
        for (int nt = 0; nt < 4; nt++) {
            C[nt][0] = C[nt][1] = C[nt][2] = C[nt][3] = 0.f;
            uint32_t h0, h1, h2, h3, e0, e1, e2, e3;
            ldsm_x4(h0, h1, h2, h3, kb + nt * 640 + aoff);
            ldsm_x4(e0, e1, e2, e3, kb + 2560 + nt * 640 + aoff);
            mma_f16(C[nt], qh[0], h0, h1);  mma_f16(C[nt], ql[0], h0, h1);  mma_f16(C[nt], qh[0], e0, e1);
            mma_f16(C[nt], qh[1], h2, h3);  mma_f16(C[nt], ql[1], h2, h3);  mma_f16(C[nt], qh[1], e2, e3);
        }

        // ---- softmax, exp2 domain ----
        float t0 = -1e30f, t1 = -1e30f;
        #pragma unroll
        for (int nt = 0; nt < 4; nt++) {
            t0 = fmaxf(t0, fmaxf(C[nt][0], C[nt][1]));
            t1 = fmaxf(t1, fmaxf(C[nt][2], C[nt][3]));
        }
        t0 = fmaxf(t0, __shfl_xor_sync(0xffffffffu, t0, 1));
        t0 = fmaxf(t0, __shfl_xor_sync(0xffffffffu, t0, 2));
        t1 = fmaxf(t1, __shfl_xor_sync(0xffffffffu, t1, 1));
        t1 = fmaxf(t1, __shfl_xor_sync(0xffffffffu, t1, 2));
        float mn0 = fmaxf(mr0, t0), mn1 = fmaxf(mr1, t1);
        float al0 = ex2f(mr0 - mn0), al1 = ex2f(mr1 - mn1);
        mr0 = mn0; mr1 = mn1;

        uint32_t P[4][2];
        float rs0 = 0.f, rs1 = 0.f;
        #pragma unroll
        for (int nt = 0; nt < 4; nt++) {
            float p0 = ex2f(C[nt][0] - mn0), p1 = ex2f(C[nt][1] - mn0);
            float p2 = ex2f(C[nt][2] - mn1), p3 = ex2f(C[nt][3] - mn1);
            __half2 h01 = __floats2half2_rn(p0, p1);
            __half2 h23 = __floats2half2_rn(p2, p3);
            P[nt][0] = h2u(h01); P[nt][1] = h2u(h23);
            float2 f01 = __half22float2(h01), f23 = __half22float2(h23);
            rs0 += f01.x + f01.y; rs1 += f23.x + f23.y;
        }
        rs0 += __shfl_xor_sync(0xffffffffu, rs0, 1);
        rs0 += __shfl_xor_sync(0xffffffffu, rs0, 2);
        rs1 += __shfl_xor_sync(0xffffffffu, rs1, 1);
        rs1 += __shfl_xor_sync(0xffffffffu, rs1, 2);
        lr0 = lr0 * al0 + rs0;
        lr1 = lr1 * al1 + rs1;

        if (__any_sync(0xffffffffu, (al0 != 1.f) || (al1 != 1.f))) {
            #pragma unroll
            for (int nt = 0; nt < 32; nt++) {
                O[nt][0] *= al0; O[nt][1] *= al0;
                O[nt][2] *= al1; O[nt][3] *= al1;
            }
        }

        // ---- O += P V ----
        uint32_t pa0[4] = { P[0][0], P[0][1], P[1][0], P[1][1] };
        uint32_t pa1[4] = { P[2][0], P[2][1], P[3][0], P[3][1] };
        const uint32_t vb = smb + OFF_V + s * 20480;
        #pragma unroll
        for (int nt = 0; nt < 32; nt++) {
            uint32_t b00, b01, b10, b11;
            ldsm_x4(b00, b01, b10, b11, vb + nt * 640 + aoff);
            mma_f16(O[nt], pa0, b00, b01);
            mma_f16(O[nt], pa1, b10, b11);
        }

        // ---- this warp done reading slot s ----
        __syncwarp();
        if (lane == 0) MBAR_ARRIVE(mb_empty + 8 * s);
    }

    // ---- epilogue ----
    const float linv0 = 1.0f / lr0;
    const float linv1 = 1.0f / lr1;
    const float gam = __ldg(gamma);
    #pragma unroll
    for (int nt = 0; nt < 32; nt++) {
        #pragma unroll
        for (int e = 0; e < 4; e++) {
            int c   = 8 * nt + 2 * m + (e & 1);
            int row = iw + g + 8 * (e >> 1);
            size_t idx = (((size_t)(n * CC + c)) << 12) + i0 + row;
            float o = O[nt][e] * ((e >> 1) ? linv1 : linv0);
            out[idx] = gam * o + __ldg(&x[idx]);
        }
    }
}

// ---------------- launch -----------------------------------------------------
extern "C" void kernel_launch(void* const* d_in, const int* in_sizes, int n_in,
                              void* d_out, int out_size) {
    const float* x     = (const float*)d_in[0];
    const float* Wq    = (const float*)d_in[1];
    const float* bq    = (const float*)d_in[2];
    const float* Wk    = (const float*)d_in[3];
    const float* bk    = (const float*)d_in[4];
    const float* Wv    = (const float*)d_in[5];
    const float* bv    = (const float*)d_in[6];
    const float* gamma = (const float*)d_in[7];
    float* out = (float*)d_out;

    cudaFuncSetAttribute(proj_kernel, cudaFuncAttributeMaxDynamicSharedMemorySize, PROJ_SMEM);
    cudaFuncSetAttribute(attn_kernel, cudaFuncAttributeMaxDynamicSharedMemorySize, ATTN_SMEM);

    wtrans_kernel<<<320, 256>>>(Wq, Wk, Wv);
    proj_kernel<<<dim3(LL / 64, 5, NB), 128, PROJ_SMEM>>>(x, bq, bk, bv);
    attn_kernel<<<dim3(LL / BI, NB), 128, ATTN_SMEM>>>(x, gamma, out);
}

// round 12
// speedup vs baseline: 3.4498x; 1.1930x over previous
#include <cuda_runtime.h>
#include <cuda_fp16.h>
#include <cstdint>

#define NB   8
#define CC   256
#define CQK  32
#define LL   4096
#define BI   64
#define BJ   64
#define NJT  (LL / BJ)          // 64 j-tiles
#define INVLN2 1.4426950408889634f

// ---------------- scratch (device globals) ----------------------------------
__device__ __half g_Wh [320 * 256];                 // fused weights fp16-hi, (o, c)
__device__ __half g_Wql[64 * 256];                  // fp16-lo residual, q/k rows only
__device__ __half g_qh [NB * LL * CQK];             // (N, L, 32) token-major fp16-hi
__device__ __half g_ql [NB * LL * CQK];
__device__ __half g_kh [NB * LL * CQK];             // (N, L, 32) fp16-hi (scaled 1/ln2)
__device__ __half g_kl [NB * LL * CQK];
__device__ __half g_v  [(size_t)NB * CC * LL];      // (N, C, L) fp16, l contiguous

// ---------------- helpers ----------------------------------------------------
__device__ __forceinline__ uint32_t smem_u32(const void* p) {
    uint32_t a;
    asm("{ .reg .u64 t; cvta.to.shared.u64 t, %1; cvt.u32.u64 %0, t; }" : "=r"(a) : "l"(p));
    return a;
}
__device__ __forceinline__ void cp_async16(uint32_t dst, const void* src) {
    asm volatile("cp.async.cg.shared.global [%0], [%1], 16;"
                 :: "r"(dst), "l"((unsigned long long)__cvta_generic_to_global(src)) : "memory");
}
#define CP_COMMIT() asm volatile("cp.async.commit_group;" ::: "memory")
#define CP_WAIT0()  asm volatile("cp.async.wait_group 0;" ::: "memory")
#define CP_WAIT1()  asm volatile("cp.async.wait_group 1;" ::: "memory")

// mbarrier (sm_80+/sm_90 baseline PTX; no arch-'a' features)
#define MBARRIER_INIT(mbar, cnt) \
    asm volatile("mbarrier.init.shared.b64 [%0], %1;" :: "r"((uint32_t)(mbar)), "r"((uint32_t)(cnt)) : "memory")
#define MBAR_ARRIVE(mbar) \
    asm volatile("mbarrier.arrive.shared::cta.b64 _, [%0];" :: "r"((uint32_t)(mbar)) : "memory")
// NOTE: .noinc is load-bearing (default form pre-increments -> deadlock).
#define CP_MBAR_ARRIVE(mbar) \
    asm volatile("cp.async.mbarrier.arrive.noinc.shared::cta.b64 [%0];" :: "r"((uint32_t)(mbar)) : "memory")
#define MBARRIER_WAIT_PARITY(mbar, parity) do { \
    uint32_t _m = (uint32_t)(mbar); uint32_t _p = (uint32_t)(parity); uint32_t _d; \
    asm volatile("{\n\t.reg .pred p;\n\t" \
        "mbarrier.try_wait.parity.acquire.cta.shared::cta.b64 p, [%1], %2;\n\t" \
        "selp.b32 %0, 1, 0, p;\n\t}" : "=r"(_d) : "r"(_m), "r"(_p) : "memory"); \
    if (!_d) { \
        asm volatile("{\n\t.reg .pred P1;\n\t" \
            "WAIT_LOOP_%=:\n\t" \
            "mbarrier.try_wait.parity.acquire.cta.shared::cta.b64 P1, [%0], %1, 0x989680;\n\t" \
            "@P1 bra.uni WAIT_DONE_%=;\n\t" \
            "bra.uni WAIT_LOOP_%=;\n\t" \
            "WAIT_DONE_%=:\n\t}" :: "r"(_m), "r"(_p) : "memory"); \
    } \
} while (0)

__device__ __forceinline__ uint32_t h2u(__half2 h) { return *reinterpret_cast<uint32_t*>(&h); }
__device__ __forceinline__ float ex2f(float x) {
    float r;
    asm("ex2.approx.f32 %0, %1;" : "=f"(r) : "f"(x));
    return r;
}
__device__ __forceinline__ void ldsm_x4(uint32_t& r0, uint32_t& r1, uint32_t& r2, uint32_t& r3,
                                        uint32_t addr) {
    asm volatile("ldmatrix.sync.aligned.m8n8.x4.shared.b16 {%0,%1,%2,%3}, [%4];"
                 : "=r"(r0), "=r"(r1), "=r"(r2), "=r"(r3) : "r"(addr));
}
__device__ __forceinline__ void ldsm_x4a(uint32_t r[4], uint32_t addr) {
    ldsm_x4(r[0], r[1], r[2], r[3], addr);
}
__device__ __forceinline__ void mma_f16(float c[4], const uint32_t a[4],
                                        uint32_t b0, uint32_t b1) {
    asm("mma.sync.aligned.m16n8k16.row.col.f32.f16.f16.f32 "
        "{%0,%1,%2,%3}, {%4,%5,%6,%7}, {%8,%9}, {%0,%1,%2,%3};"
        : "+f"(c[0]), "+f"(c[1]), "+f"(c[2]), "+f"(c[3])
        : "r"(a[0]), "r"(a[1]), "r"(a[2]), "r"(a[3]), "r"(b0), "r"(b1));
}

// ---------------- kernel 1: weight prep (fp16 hi + q/k lo residual) ----------
__global__ void wtrans_kernel(const float* __restrict__ Wq,
                              const float* __restrict__ Wk,
                              const float* __restrict__ Wv) {
    int idx = blockIdx.x * 256 + threadIdx.x;
    if (idx >= 320 * 256) return;
    int o = idx >> 8, c = idx & 255;
    float v;
    if (o < 32)       v = Wq[o * 256 + c];
    else if (o < 64)  v = Wk[(o - 32) * 256 + c];
    else              v = Wv[(o - 64) * 256 + c];
    __half h = __float2half_rn(v);
    g_Wh[o * 256 + c] = h;
    if (o < 64) g_Wql[o * 256 + c] = __float2half_rn(v - __half2float(h));
}

// ---------------- kernel 2: tensor-core fused QKV projection ------------------
#define PJ_XH 0
#define PJ_XL 33792
#define PJ_WH 67584        // 3 slots x 5120
#define PJ_WL 82944        // 3 slots x 5120 (q/k CTAs only)
#define PROJ_SMEM 98304

__global__ __launch_bounds__(128, 2)
void proj_kernel(const float* __restrict__ x,
                 const float* __restrict__ bq,
                 const float* __restrict__ bk,
                 const float* __restrict__ bv) {
    extern __shared__ char sm[];
    const uint32_t smb = smem_u32(sm);
    const int tid = threadIdx.x;
    const int wid = tid >> 5, lane = tid & 31;
    const int g = lane >> 2, m = lane & 3;
    const int n = blockIdx.z;
    const int oidx = blockIdx.y;
    const int l0 = blockIdx.x * 64;
    const int obase = oidx * 64;
    const bool qk = (oidx == 0);

    auto issueW = [&](int r, int slot) {
        #pragma unroll
        for (int k = 0; k < 2; k++) {
            int idx = tid * 2 + k;          // 0..255
            int row = idx >> 2, seg = idx & 3;
            cp_async16(smb + PJ_WH + slot * 5120 + row * 80 + seg * 16,
                       g_Wh + (obase + row) * 256 + r * 32 + seg * 8);
            if (qk)
                cp_async16(smb + PJ_WL + slot * 5120 + row * 80 + seg * 16,
                           g_Wql + row * 256 + r * 32 + seg * 8);
        }
        CP_COMMIT();
    };
    issueW(0, 0);
    issueW(1, 1);

    {
        const float* xb = x + ((size_t)n << 20) + l0;
        const int l = tid & 63, p0 = tid >> 6;
        #pragma unroll 4
        for (int i = 0; i < 64; i++) {
            int p = p0 + 2 * i;
            int c = 2 * p;
            float f0 = __ldg(&xb[(size_t)c * 4096 + l]);
            float f1 = __ldg(&xb[(size_t)(c + 1) * 4096 + l]);
            __half h0 = __float2half_rn(f0), h1 = __float2half_rn(f1);
            __half e0 = __float2half_rn(f0 - __half2float(h0));
            __half e1 = __float2half_rn(f1 - __half2float(h1));
            *(uint32_t*)(sm + PJ_XH + l * 528 + p * 4) = h2u(__halves2half2(h0, h1));
            *(uint32_t*)(sm + PJ_XL + l * 528 + p * 4) = h2u(__halves2half2(e0, e1));
        }
    }

    float C[8][4];
    #pragma unroll
    for (int og = 0; og < 8; og++)
        #pragma unroll
        for (int e = 0; e < 4; e++) C[og][e] = 0.f;

    const uint32_t aoffA = (uint32_t)((lane & 15) * 528 + (lane >> 4) * 16);
    const uint32_t aoffB = (uint32_t)((lane & 7) * 80 + (lane >> 3) * 16);
    const uint32_t abase = smb + (uint32_t)(wid * 16) * 528;

    for (int r = 0; r < 8; r++) {
        const int slot = r % 3;
        if (r == 7) { CP_WAIT0(); } else { CP_WAIT1(); }
        __syncthreads();
        if (r + 2 < 8) issueW(r + 2, (r + 2) % 3);

        uint32_t axh0[4], axh1[4], axl0[4], axl1[4];
        ldsm_x4a(axh0, abase + PJ_XH + r * 64 + aoffA);
        ldsm_x4a(axh1, abase + PJ_XH + r * 64 + 32 + aoffA);
        ldsm_x4a(axl0, abase + PJ_XL + r * 64 + aoffA);
        ldsm_x4a(axl1, abase + PJ_XL + r * 64 + 32 + aoffA);

        const uint32_t wb  = smb + PJ_WH + slot * 5120;
        const uint32_t wlb = smb + PJ_WL + slot * 5120;
        #pragma unroll
        for (int og = 0; og < 8; og++) {
            uint32_t b0, b1, b2, b3;
            ldsm_x4(b0, b1, b2, b3, wb + og * 640 + aoffB);
            mma_f16(C[og], axh0, b0, b1);
            mma_f16(C[og], axl0, b0, b1);
            mma_f16(C[og], axh1, b2, b3);
            mma_f16(C[og], axl1, b2, b3);
            if (qk) {
                uint32_t c0, c1, c2, c3;
                ldsm_x4(c0, c1, c2, c3, wlb + og * 640 + aoffB);
                mma_f16(C[og], axh0, c0, c1);
                mma_f16(C[og], axh1, c2, c3);
            }
        }
    }
    __syncthreads();

    if (qk) {
        #pragma unroll
        for (int og = 0; og < 8; og++) {
            int ol = og * 8 + 2 * m;
            bool isq = (ol < 32);
            float sc = isq ? 1.0f : INVLN2;
            const float* bias = isq ? bq : bk;
            int bo = isq ? ol : ol - 32;
            float b0 = __ldg(&bias[bo]), b1 = __ldg(&bias[bo + 1]);
            uint32_t* dsth = (uint32_t*)(isq ? g_qh : g_kh);
            uint32_t* dstl = (uint32_t*)(isq ? g_ql : g_kl);
            int col = (isq ? og * 4 : (og - 4) * 4) + m;
            #pragma unroll
            for (int rr = 0; rr < 2; rr++) {
                float f0 = (C[og][2 * rr]     + b0) * sc;
                float f1 = (C[og][2 * rr + 1] + b1) * sc;
                __half h0 = __float2half_rn(f0), h1 = __float2half_rn(f1);
                __half e0 = __float2half_rn(f0 - __half2float(h0));
                __half e1 = __float2half_rn(f1 - __half2float(h1));
                size_t lg = (size_t)(n << 12) + l0 + wid * 16 + g + 8 * rr;
                dsth[lg * 16 + col] = h2u(__halves2half2(h0, h1));
                dstl[lg * 16 + col] = h2u(__halves2half2(e0, e1));
            }
        }
    } else {
        __half* bo = (__half*)sm;            // [64 o][72 l]
        const int vb0 = (oidx - 1) * 64;
        #pragma unroll
        for (int og = 0; og < 8; og++) {
            int ol = og * 8 + 2 * m;
            float b0 = __ldg(&bv[vb0 + ol]), b1 = __ldg(&bv[vb0 + ol + 1]);
            int lg = wid * 16 + g;
            bo[ol * 72 + lg]           = __float2half_rn(C[og][0] + b0);
            bo[(ol + 1) * 72 + lg]     = __float2half_rn(C[og][1] + b1);
            bo[ol * 72 + lg + 8]       = __float2half_rn(C[og][2] + b0);
            bo[(ol + 1) * 72 + lg + 8] = __float2half_rn(C[og][3] + b1);
        }
        __syncthreads();
        const int o = tid >> 1, lh = tid & 1;
        const uint4* src = (const uint4*)(sm + o * 144 + lh * 64);
        uint4* dst = (uint4*)(g_v + (((size_t)(n * CC + vb0 + o)) << 12) + l0 + lh * 32);
        #pragma unroll
        for (int i = 0; i < 4; i++) dst[i] = src[i];
    }
}

// ---------------- kernel 3: BJ=64 mbarrier-skewed fp16 flash attention -------
// 2-slot K/V ring. K rows 80 B stride (5x16B, odd -> ldsm conflict-free);
// V rows 144 B stride (9x16B, odd -> conflict-free).
#define OFF_QH 0            // [64][40] fp16
#define OFF_QL 5120
#define OFF_K  10240        // 2 slots x 10240: [KH 64][40] then [KL 64][40]
#define OFF_V  30720        // 2 slots x 36864: [256][72] fp16
#define OFF_MB 104448       // full[0..1] at +0, empty[0..1] at +16
#define ATTN_SMEM 104704

__device__ __forceinline__ void loadK(uint32_t smb, int n, int j0, int slot, int tid) {
    const uint32_t kbase = smb + OFF_K + slot * 10240;
    #pragma unroll
    for (int it = 0; it < 4; it++) {
        int idx = it * 128 + tid;        // 0..511
        int hl = idx >> 8;
        int r  = (idx >> 2) & 63;
        int s  = idx & 3;
        const __half* src = (hl ? g_kl : g_kh) + ((size_t)((n << 12) + j0 + r)) * 32 + s * 8;
        cp_async16(kbase + hl * 5120 + r * 80 + s * 16, src);
    }
}
__device__ __forceinline__ void loadV(uint32_t smb, int n, int j0, int slot, int tid) {
    const uint32_t vbase = smb + OFF_V + slot * 36864;
    #pragma unroll
    for (int it = 0; it < 16; it++) {
        int idx = it * 128 + tid;        // 0..2047
        int cr = idx >> 3;               // 0..255
        int s  = idx & 7;
        const __half* src = g_v + (((size_t)n * CC + cr) << 12) + j0 + s * 8;
        cp_async16(vbase + cr * 144 + s * 16, src);
    }
}

__global__ __launch_bounds__(128, 2)
void attn_kernel(const float* __restrict__ x,
                 const float* __restrict__ gamma,
                 float* __restrict__ out) {
    extern __shared__ char sm[];
    const uint32_t smb = smem_u32(sm);
    const int tid  = threadIdx.x;
    const int wid  = tid >> 5, lane = tid & 31;
    const int g    = lane >> 2, m = lane & 3;
    const int iw   = wid * 16;
    const int n    = blockIdx.y;
    const int i0   = blockIdx.x * BI;

    const uint32_t aoffK = (uint32_t)((lane & 7) * 80 + (lane >> 3) * 16);
    const uint32_t aoffV = (uint32_t)((lane & 7) * 144 + (lane >> 3) * 16);
    const uint32_t mb_full  = smb + OFF_MB;
    const uint32_t mb_empty = smb + OFF_MB + 16;

    if (tid == 0) {
        #pragma unroll
        for (int s = 0; s < 2; s++) {
            MBARRIER_INIT(mb_full + 8 * s, 128);
            MBARRIER_INIT(mb_empty + 8 * s, 4);
        }
    }

    // ---- Q tile via plain ld/st ----
    #pragma unroll
    for (int it = 0; it < 4; it++) {
        int idx  = it * 128 + tid;          // 0..511
        int half = idx >> 8;
        int r    = (idx >> 2) & 63;
        int s    = idx & 3;
        const __half* src = (half ? g_ql : g_qh) + ((size_t)((n << 12) + i0 + r)) * 32 + s * 8;
        uint4 v = *(const uint4*)src;
        *(uint4*)(sm + (half ? OFF_QL : OFF_QH) + r * 80 + s * 16) = v;
    }
    __syncthreads();   // mbarrier init + Q visible

    // ---- prologue: fill slots 0,1 (tiles 0,1) ----
    #pragma unroll
    for (int t = 0; t < 2; t++) {
        loadK(smb, n, t * BJ, t, tid);
        loadV(smb, n, t * BJ, t, tid);
        CP_MBAR_ARRIVE(mb_full + 8 * t);
    }

    // ---- Q fragments ----
    uint32_t qh[2][4], ql[2][4];
    {
        const uint32_t* QHw = (const uint32_t*)(sm + OFF_QH);
        const uint32_t* QLw = (const uint32_t*)(sm + OFF_QL);
        #pragma unroll
        for (int kc = 0; kc < 2; kc++) {
            qh[kc][0] = QHw[(iw + g)     * 20 + 8 * kc + m];
            qh[kc][1] = QHw[(iw + g + 8) * 20 + 8 * kc + m];
            qh[kc][2] = QHw[(iw + g)     * 20 + 8 * kc + 4 + m];
            qh[kc][3] = QHw[(iw + g + 8) * 20 + 8 * kc + 4 + m];
            ql[kc][0] = QLw[(iw + g)     * 20 + 8 * kc + m];
            ql[kc][1] = QLw[(iw + g + 8) * 20 + 8 * kc + m];
            ql[kc][2] = QLw[(iw + g)     * 20 + 8 * kc + 4 + m];
            ql[kc][3] = QLw[(iw + g + 8) * 20 + 8 * kc + 4 + m];
        }
    }

    float O[32][4];
    #pragma unroll
    for (int nt = 0; nt < 32; nt++)
        #pragma unroll
        for (int e = 0; e < 4; e++) O[nt][e] = 0.f;
    float mr0 = -1e30f, mr1 = -1e30f, lr0 = 0.f, lr1 = 0.f;

    for (int jt = 0; jt < NJT; jt++) {
        const int s = jt & 1;

        // ---- per-warp prefetch of tile jt+1 into the other slot ----
        if (jt >= 1 && jt + 1 < NJT) {
            const int t2 = jt + 1;
            const int s2 = t2 & 1;
            MBARRIER_WAIT_PARITY(mb_empty + 8 * s2, (uint32_t)(((t2 >> 1) - 1) & 1));
            loadK(smb, n, t2 * BJ, s2, tid);
            loadV(smb, n, t2 * BJ, s2, tid);
            CP_MBAR_ARRIVE(mb_full + 8 * s2);
        }

        // ---- wait data ----
        MBARRIER_WAIT_PARITY(mb_full + 8 * s, (uint32_t)((jt >> 1) & 1));

        // ---- S = Q K^T (3-term fp16 split), 64 j per tile ----
        const uint32_t kb = smb + OFF_K + s * 10240;
        float C[8][4];
        #pragma unroll
        for (int nt = 0; nt < 8; nt++) {
            C[nt][0] = C[nt][1] = C[nt][2] = C[nt][3] = 0.f;
            uint32_t h0, h1, h2, h3, e0, e1, e2, e3;
            ldsm_x4(h0, h1, h2, h3, kb + nt * 640 + aoffK);
            ldsm_x4(e0, e1, e2, e3, kb + 5120 + nt * 640 + aoffK);
            mma_f16(C[nt], qh[0], h0, h1);  mma_f16(C[nt], ql[0], h0, h1);  mma_f16(C[nt], qh[0], e0, e1);
            mma_f16(C[nt], qh[1], h2, h3);  mma_f16(C[nt], ql[1], h2, h3);  mma_f16(C[nt], qh[1], e2, e3);
        }

        // ---- softmax, exp2 domain ----
        float t0 = -1e30f, t1 = -1e30f;
        #pragma unroll
        for (int nt = 0; nt < 8; nt++) {
            t0 = fmaxf(t0, fmaxf(C[nt][0], C[nt][1]));
            t1 = fmaxf(t1, fmaxf(C[nt][2], C[nt][3]));
        }
        t0 = fmaxf(t0, __shfl_xor_sync(0xffffffffu, t0, 1));
        t0 = fmaxf(t0, __shfl_xor_sync(0xffffffffu, t0, 2));
        t1 = fmaxf(t1, __shfl_xor_sync(0xffffffffu, t1, 1));
        t1 = fmaxf(t1, __shfl_xor_sync(0xffffffffu, t1, 2));
        float mn0 = fmaxf(mr0, t0), mn1 = fmaxf(mr1, t1);
        float al0 = ex2f(mr0 - mn0), al1 = ex2f(mr1 - mn1);
        mr0 = mn0; mr1 = mn1;

        uint32_t P[8][2];
        float rs0 = 0.f, rs1 = 0.f;
        #pragma unroll
        for (int nt = 0; nt < 8; nt++) {
            float p0 = ex2f(C[nt][0] - mn0), p1 = ex2f(C[nt][1] - mn0);
            float p2 = ex2f(C[nt][2] - mn1), p3 = ex2f(C[nt][3] - mn1);
            __half2 h01 = __floats2half2_rn(p0, p1);
            __half2 h23 = __floats2half2_rn(p2, p3);
            P[nt][0] = h2u(h01); P[nt][1] = h2u(h23);
            float2 f01 = __half22float2(h01), f23 = __half22float2(h23);
            rs0 += f01.x + f01.y; rs1 += f23.x + f23.y;
        }
        rs0 += __shfl_xor_sync(0xffffffffu, rs0, 1);
        rs0 += __shfl_xor_sync(0xffffffffu, rs0, 2);
        rs1 += __shfl_xor_sync(0xffffffffu, rs1, 1);
        rs1 += __shfl_xor_sync(0xffffffffu, rs1, 2);
        lr0 = lr0 * al0 + rs0;
        lr1 = lr1 * al1 + rs1;

        if (__any_sync(0xffffffffu, (al0 != 1.f) || (al1 != 1.f))) {
            #pragma unroll
            for (int nt = 0; nt < 32; nt++) {
                O[nt][0] *= al0; O[nt][1] *= al0;
                O[nt][2] *= al1; O[nt][3] *= al1;
            }
        }

        // ---- O += P V  (64 j = 4 k-chunks of 16) ----
        uint32_t pa[4][4];
        #pragma unroll
        for (int kc = 0; kc < 4; kc++) {
            pa[kc][0] = P[2 * kc][0];     pa[kc][1] = P[2 * kc][1];
            pa[kc][2] = P[2 * kc + 1][0]; pa[kc][3] = P[2 * kc + 1][1];
        }
        const uint32_t vb = smb + OFF_V + s * 36864;
        #pragma unroll
        for (int nt = 0; nt < 32; nt++) {
            uint32_t b00, b01, b10, b11, c00, c01, c10, c11;
            ldsm_x4(b00, b01, b10, b11, vb + nt * 1152 + aoffV);
            ldsm_x4(c00, c01, c10, c11, vb + nt * 1152 + 64 + aoffV);
            mma_f16(O[nt], pa[0], b00, b01);
            mma_f16(O[nt], pa[1], b10, b11);
            mma_f16(O[nt], pa[2], c00, c01);
            mma_f16(O[nt], pa[3], c10, c11);
        }

        // ---- this warp done reading slot s ----
        __syncwarp();
        if (lane == 0) MBAR_ARRIVE(mb_empty + 8 * s);
    }

    // ---- epilogue ----
    const float linv0 = 1.0f / lr0;
    const float linv1 = 1.0f / lr1;
    const float gam = __ldg(gamma);
    #pragma unroll
    for (int nt = 0; nt < 32; nt++) {
        #pragma unroll
        for (int e = 0; e < 4; e++) {
            int c   = 8 * nt + 2 * m + (e & 1);
            int row = iw + g + 8 * (e >> 1);
            size_t idx = (((size_t)(n * CC + c)) << 12) + i0 + row;
            float o = O[nt][e] * ((e >> 1) ? linv1 : linv0);
            out[idx] = gam * o + __ldg(&x[idx]);
        }
    }
}

// ---------------- launch -----------------------------------------------------
extern "C" void kernel_launch(void* const* d_in, const int* in_sizes, int n_in,
                              void* d_out, int out_size) {
    const float* x     = (const float*)d_in[0];
    const float* Wq    = (const float*)d_in[1];
    const float* bq    = (const float*)d_in[2];
    const float* Wk    = (const float*)d_in[3];
    const float* bk    = (const float*)d_in[4];
    const float* Wv    = (const float*)d_in[5];
    const float* bv    = (const float*)d_in[6];
    const float* gamma = (const float*)d_in[7];
    float* out = (float*)d_out;

    cudaFuncSetAttribute(proj_kernel, cudaFuncAttributeMaxDynamicSharedMemorySize, PROJ_SMEM);
    cudaFuncSetAttribute(attn_kernel, cudaFuncAttributeMaxDynamicSharedMemorySize, ATTN_SMEM);

    wtrans_kernel<<<320, 256>>>(Wq, Wk, Wv);
    proj_kernel<<<dim3(LL / 64, 5, NB), 128, PROJ_SMEM>>>(x, bq, bk, bv);
    attn_kernel<<<dim3(LL / BI, NB), 128, ATTN_SMEM>>>(x, gamma, out);
}